// round 17
// baseline (speedup 1.0000x reference)
#include <cuda_runtime.h>
#include <cuda_fp16.h>

#define NTOK  8192
#define NCODE 8192
#define DDIM  256
#define NSPLIT 2
#define CPS   (NCODE / NSPLIT)
#define NTI   (CPS / 128)          /* 32 n-tiles per CTA */
#define ROWB  528                  /* smem row stride bytes (264 halves) */
#define A_BYTES 67584              /* 128 x 528 */
#define B_BYTES 67584
#define SMAX_OFF (A_BYTES + 2 * B_BYTES)
#define SM_TOT   (SMAX_OFF + 512)  /* + s_max[128] u32 */

typedef unsigned int u32;
typedef unsigned long long u64;

__device__ __align__(16) __half g_za[NTOK * DDIM];
__device__ __align__(16) __half g_cb[NCODE * DDIM];
__device__ u32 g_cnt[NTOK];
__device__ u32 g_listv[NTOK][64];

__device__ __forceinline__ u32 s2u(const void* p) {
    u32 a;
    asm("{ .reg .u64 t; cvta.to.shared.u64 t, %1; cvt.u32.u64 %0, t; }" : "=r"(a) : "l"(p));
    return a;
}
__device__ __forceinline__ const float* zptr(const float* a, const float* b) {
    float m = 0.f;
#pragma unroll
    for (int i = 0; i < 8; i++) m += fabsf(a[i]);
    return (m > 0.01f) ? a : b;
}
__device__ __forceinline__ u32 ordu(float v) {
    u32 u = __float_as_uint(v);
    return ((int)u < 0) ? ~u : (u | 0x80000000u);
}
__device__ __forceinline__ float dec(u32 o) {
    return (o & 0x80000000u) ? __uint_as_float(o & 0x7FFFFFFFu) : __uint_as_float(~o);
}
__device__ __forceinline__ void mma16816(float* d, u32 a0, u32 a1, u32 a2, u32 a3,
                                         u32 b0, u32 b1) {
    asm volatile(
        "mma.sync.aligned.m16n8k16.row.col.f32.f16.f16.f32 "
        "{%0,%1,%2,%3}, {%4,%5,%6,%7}, {%8,%9}, {%0,%1,%2,%3};"
        : "+f"(d[0]), "+f"(d[1]), "+f"(d[2]), "+f"(d[3])
        : "r"(a0), "r"(a1), "r"(a2), "r"(a3), "r"(b0), "r"(b1));
}
__device__ __forceinline__ void cpa16(u32 dst, const void* src) {
    asm volatile("cp.async.ca.shared.global [%0], [%1], 16;" :: "r"(dst), "l"(src));
}

__global__ void k_reset() {
    int i = blockIdx.x * blockDim.x + threadIdx.x;
    if (i < NTOK) g_cnt[i] = 0u;
}

__global__ void k_half_z(const float* i0, const float* i1) {
    __shared__ __half sh[32][264];
    const float* z = zptr(i0, i1);
    int i0b = blockIdx.x * 32;
    int bb = i0b >> 10, t0 = i0b & 1023;
    int tid = threadIdx.x, tl = tid & 31, kl = tid >> 5;
#pragma unroll 4
    for (int r = 0; r < 32; r++) {
        int k = kl + r * 8;
        sh[tl][k] = __float2half_rn(z[(size_t)bb * DDIM * 1024 + (size_t)k * 1024 + t0 + tl]);
    }
    __syncthreads();
#pragma unroll
    for (int r = 0; r < 8; r++) {
        int e = tid + 256 * r, row = e >> 6, w = e & 63;
        *(u64*)&g_za[(size_t)(i0b + row) * DDIM + w * 4] = *(u64*)&sh[row][w * 4];
    }
}

__global__ void k_half_cb(const float* i0, const float* i1) {
    const float* z = zptr(i0, i1);
    const float* cb = (z == i0) ? i1 : i0;
    int g = blockIdx.x * blockDim.x + threadIdx.x;
    if (g >= NCODE * DDIM / 4) return;
    float4 v = *(const float4*)&cb[(size_t)g * 4];
    union { __half h[4]; u64 u; } H;
    H.h[0] = __float2half_rn(v.x * 4096.f);
    H.h[1] = __float2half_rn(v.y * 4096.f);
    H.h[2] = __float2half_rn(v.z * 4096.f);
    H.h[3] = __float2half_rn(v.w * 4096.f);
    *(u64*)&g_cb[(size_t)g * 4] = H.u;
}

// single fused pass: GEMM + running per-token max + candidate append
__global__ void __launch_bounds__(256, 1) vq_gemm() {
    extern __shared__ char sm[];
    const u32 smb = s2u(sm);
    u32* s_max = (u32*)(sm + SMAX_OFF);
    const int tid = threadIdx.x, wid = tid >> 5, lane = tid & 31;
    const int mw = wid & 3, nw = wid >> 2, lq = lane >> 2, lc = lane & 3;
    const int m0 = blockIdx.x * 128, nb = blockIdx.y * CPS;

    if (tid < 128) s_max[tid] = 0u;   // ordered -inf

#pragma unroll
    for (int q = 0; q < 16; q++) {
        int idx = tid + 256 * q, r = idx >> 5, kg = idx & 31;
        cpa16(smb + r * ROWB + kg * 16, &g_za[(size_t)(m0 + r) * DDIM + kg * 8]);
    }
#pragma unroll
    for (int q = 0; q < 16; q++) {
        int idx = tid + 256 * q, r = idx >> 5, kg = idx & 31;
        cpa16(smb + A_BYTES + r * ROWB + kg * 16, &g_cb[(size_t)(nb + r) * DDIM + kg * 8]);
    }
    asm volatile("cp.async.commit_group;");

    for (int nt = 0; nt < NTI; nt++) {
        int buf = nt & 1;
        if (nt + 1 < NTI) {
            int r2 = nb + (nt + 1) * 128;
            u32 boff = A_BYTES + (u32)(((nt + 1) & 1) * B_BYTES);
#pragma unroll
            for (int q = 0; q < 16; q++) {
                int idx = tid + 256 * q, r = idx >> 5, kg = idx & 31;
                cpa16(smb + boff + r * ROWB + kg * 16, &g_cb[(size_t)(r2 + r) * DDIM + kg * 8]);
            }
            asm volatile("cp.async.commit_group;");
            asm volatile("cp.async.wait_group 1;");
        } else {
            asm volatile("cp.async.wait_group 0;");
        }
        __syncthreads();

        float acc[2][8][4];
#pragma unroll
        for (int i = 0; i < 2; i++)
#pragma unroll
            for (int j = 0; j < 8; j++)
#pragma unroll
                for (int c = 0; c < 4; c++) acc[i][j][c] = 0.f;

        const char* B_ = sm + A_BYTES + (size_t)buf * B_BYTES;
#pragma unroll 4
        for (int ks = 0; ks < 16; ks++) {
            int k0 = ks * 16;
            u32 a[2][4];
#pragma unroll
            for (int i = 0; i < 2; i++) {
                const char* ar = sm + (mw * 32 + i * 16 + lq) * ROWB + (k0 + lc * 2) * 2;
                a[i][0] = *(const u32*)(ar);
                a[i][1] = *(const u32*)(ar + 8 * ROWB);
                a[i][2] = *(const u32*)(ar + 16);
                a[i][3] = *(const u32*)(ar + 8 * ROWB + 16);
            }
#pragma unroll
            for (int j = 0; j < 8; j++) {
                const char* br = B_ + (nw * 64 + j * 8 + lq) * ROWB + (k0 + lc * 2) * 2;
                u32 b0 = *(const u32*)(br);
                u32 b1 = *(const u32*)(br + 16);
                mma16816(acc[0][j], a[0][0], a[0][1], a[0][2], a[0][3], b0, b1);
                mma16816(acc[1][j], a[1][0], a[1][1], a[1][2], a[1][3], b0, b1);
            }
        }

        // ---- running max update (slot s = i*2 + rowgroup) ----
        float mx[4] = {-1e30f, -1e30f, -1e30f, -1e30f};
#pragma unroll
        for (int i = 0; i < 2; i++)
#pragma unroll
            for (int j = 0; j < 8; j++) {
                mx[i * 2 + 0] = fmaxf(mx[i * 2 + 0], fmaxf(acc[i][j][0], acc[i][j][1]));
                mx[i * 2 + 1] = fmaxf(mx[i * 2 + 1], fmaxf(acc[i][j][2], acc[i][j][3]));
            }
#pragma unroll
        for (int s = 0; s < 4; s++) {
            float v = mx[s];
            v = fmaxf(v, __shfl_xor_sync(0xFFFFFFFFu, v, 1));
            v = fmaxf(v, __shfl_xor_sync(0xFFFFFFFFu, v, 2));
            if (lc == 0)
                atomicMax(&s_max[mw * 32 + (s >> 1) * 16 + lq + (s & 1) * 8], ordu(v));
        }
        __syncthreads();

        // ---- threshold read (deterministic post-barrier) + append ----
        float thrv[4], thr2[2];
#pragma unroll
        for (int s = 0; s < 4; s++)
            thrv[s] = dec(s_max[mw * 32 + (s >> 1) * 16 + lq + (s & 1) * 8]) - 0.25f;
        thr2[0] = fminf(thrv[0], thrv[1]);
        thr2[1] = fminf(thrv[2], thrv[3]);

#pragma unroll
        for (int i = 0; i < 2; i++)
#pragma unroll
            for (int j = 0; j < 8; j++) {
                float tmx = fmaxf(fmaxf(acc[i][j][0], acc[i][j][1]),
                                  fmaxf(acc[i][j][2], acc[i][j][3]));
                if (__any_sync(0xFFFFFFFFu, tmx > thr2[i])) {
#pragma unroll
                    for (int c = 0; c < 4; c++) {
                        int s = i * 2 + (c >> 1);
                        if (acc[i][j][c] > thrv[s]) {
                            int tok = m0 + mw * 32 + i * 16 + lq + (c >> 1) * 8;
                            u32 code = (u32)(nb + nt * 128 + nw * 64 + j * 8 + lc * 2 + (c & 1));
                            u32 pos = atomicAdd(&g_cnt[tok], 1u);
                            if (pos < 64u) g_listv[tok][pos] = code;
                        }
                    }
                }
            }
        __syncthreads();
    }
}

__global__ void k_rescore(const float* i0, const float* i1, float* out) {
    __shared__ float sz[DDIM];
    __shared__ float szs;
    __shared__ u64 sk[64];
    int tok = blockIdx.x, tid = threadIdx.x;
    const float* z = zptr(i0, i1);
    const float* cb = (z == i0) ? i1 : i0;
    for (int d = tid; d < DDIM; d += 64)
        sz[d] = z[(size_t)(tok >> 10) * DDIM * 1024 + (size_t)d * 1024 + (tok & 1023)];
    __syncthreads();
    if (tid == 0) {
        float acc = 0.f;
        for (int d = 0; d < DDIM; d++) acc = __fadd_rn(acc, __fmul_rn(sz[d], sz[d]));
        szs = acc;
    }
    __syncthreads();
    u32 cnt = g_cnt[tok];
    u64 key = ~0ULL;
    if (cnt <= 64u) {
        if (tid < (int)cnt) {
            u32 code = g_listv[tok][tid];
            const float* cr = cb + (size_t)code * DDIM;
            float acc = 0.f;
#pragma unroll 8
            for (int d = 0; d < DDIM; d++) acc = fmaf(sz[d], cr[d], acc);
            float dd = __fadd_rn(szs, __fmul_rn(-2.0f, acc));
            key = ((u64)ordu(dd) << 32) | code;
        }
    } else {
        // overflow fallback (expected never): exact full scan
        for (u32 code = tid; code < NCODE; code += 64) {
            const float* cr = cb + (size_t)code * DDIM;
            float acc = 0.f;
#pragma unroll 8
            for (int d = 0; d < DDIM; d++) acc = fmaf(sz[d], cr[d], acc);
            float dd = __fadd_rn(szs, __fmul_rn(-2.0f, acc));
            u64 k = ((u64)ordu(dd) << 32) | code;
            if (k < key) key = k;
        }
    }
    sk[tid] = key;
    __syncthreads();
    if (tid == 0) {
        u64 m = sk[0];
        for (int i = 1; i < 64; i++) if (sk[i] < m) m = sk[i];
        out[tok] = (float)(int)(u32)(m & 0xFFFFFFFFULL);
    }
}

extern "C" void kernel_launch(void* const* d_in, const int* in_sizes, int n_in,
                              void* d_out, int out_size) {
    const float* a = (const float*)d_in[0];
    const float* b = (const float*)d_in[1];
    cudaFuncSetAttribute(vq_gemm, cudaFuncAttributeMaxDynamicSharedMemorySize, SM_TOT);
    k_reset<<<32, 256>>>();
    k_half_z<<<NTOK / 32, 256>>>(a, b);
    k_half_cb<<<NCODE * DDIM / 4 / 256, 256>>>(a, b);
    dim3 g(NTOK / 128, NSPLIT);
    vq_gemm<<<g, 256, SM_TOT>>>();
    k_rescore<<<NTOK, 64>>>(a, b, (float*)d_out);
}